// round 16
// baseline (speedup 1.0000x reference)
#include <cuda_runtime.h>
#include <cuda_fp16.h>
#include <cstddef>
#include <cstdint>

#define T_LEN   2048
#define D_DIM   3584
#define NHEADS  28
#define KVH     4
#define HD      128
#define GRP     7
#define QCOLS   (NHEADS*HD)   // 3584
#define KCOLS   (KVH*HD)      // 512
#define SCALE_ATTN 0.08838834764831845f

// -------- scratch (no cudaMalloc allowed) --------
__device__ __half g_xh [T_LEN * D_DIM];          // x fp16
__device__ __half g_wqh[D_DIM * QCOLS];          // wq fp16 (K-major natural layout)
__device__ __half g_wkh[D_DIM * KCOLS];
__device__ __half g_wvh[D_DIM * KCOLS];
__device__ __half g_woh[QCOLS * D_DIM];          // wo fp16 [nh][d]
__device__ __half g_qh [T_LEN * QCOLS];          // rope(Q)*scale fp16
__device__ __half g_kh [T_LEN * KCOLS];          // rope(K) fp16
__device__ __half g_vh [T_LEN * KCOLS];          // V fp16
__device__ __half g_aoh[T_LEN * QCOLS];          // attention out fp16

// ---------------- helpers ----------------
__device__ __forceinline__ void cpa16(uint32_t dst, const void* src) {
    asm volatile("cp.async.cg.shared.global [%0], [%1], 16;" :: "r"(dst), "l"(src));
}
__device__ __forceinline__ void ldm4(uint32_t* r, uint32_t a) {
    asm volatile("ldmatrix.sync.aligned.m8n8.x4.shared.b16 {%0,%1,%2,%3}, [%4];"
                 : "=r"(r[0]), "=r"(r[1]), "=r"(r[2]), "=r"(r[3]) : "r"(a));
}
__device__ __forceinline__ void ldm4t(uint32_t* r, uint32_t a) {
    asm volatile("ldmatrix.sync.aligned.m8n8.x4.trans.shared.b16 {%0,%1,%2,%3}, [%4];"
                 : "=r"(r[0]), "=r"(r[1]), "=r"(r[2]), "=r"(r[3]) : "r"(a));
}
__device__ __forceinline__ void mma16(float* c, const uint32_t* a, uint32_t b0, uint32_t b1) {
    asm volatile(
        "mma.sync.aligned.m16n8k16.row.col.f32.f16.f16.f32 "
        "{%0,%1,%2,%3}, {%4,%5,%6,%7}, {%8,%9}, {%0,%1,%2,%3};"
        : "+f"(c[0]), "+f"(c[1]), "+f"(c[2]), "+f"(c[3])
        : "r"(a[0]), "r"(a[1]), "r"(a[2]), "r"(a[3]), "r"(b0), "r"(b1));
}
__device__ __forceinline__ uint32_t h2u(float a, float b) {
    __half2 h = __floats2half2_rn(a, b);
    return *reinterpret_cast<uint32_t*>(&h);
}

// =====================================================================
// merged prepass: all 5 fp32->fp16 conversions in ONE launch
// =====================================================================
#define N4_X   (T_LEN*D_DIM/4)
#define N4_WQ  (D_DIM*QCOLS/4)
#define N4_WK  (D_DIM*KCOLS/4)
#define N4_WO  (QCOLS*D_DIM/4)
#define SEG0   N4_X
#define SEG1   (SEG0 + N4_WQ)
#define SEG2   (SEG1 + N4_WK)
#define SEG3   (SEG2 + N4_WK)
#define SEGT   (SEG3 + N4_WO)

__global__ __launch_bounds__(256)
void cvt_all_kernel(const float* __restrict__ x,  const float* __restrict__ wq,
                    const float* __restrict__ wk, const float* __restrict__ wv,
                    const float* __restrict__ wo)
{
    int i = blockIdx.x * blockDim.x + threadIdx.x;
    if (i >= SEGT) return;
    const float* s; __half* d; int off;
    if (i < SEG0)      { s = x;  d = g_xh;  off = i; }
    else if (i < SEG1) { s = wq; d = g_wqh; off = i - SEG0; }
    else if (i < SEG2) { s = wk; d = g_wkh; off = i - SEG1; }
    else if (i < SEG3) { s = wv; d = g_wvh; off = i - SEG2; }
    else               { s = wo; d = g_woh; off = i - SEG3; }
    float4 v = ((const float4*)s)[off];
    ((__half2*)d)[2*off]   = __floats2half2_rn(v.x, v.y);
    ((__half2*)d)[2*off+1] = __floats2half2_rn(v.z, v.w);
}

// =====================================================================
// GEMM mainloop: CTA 128x128, BK=64, 3-stage cp.async, 128 threads,
// 4 warps (2x2), warp tile 64x64.  One barrier per 128 mma/warp.
// A stride 72 halfs; B K-major stride 136, via ldmatrix.trans.
// =====================================================================
#define ABYT  (128 * 72 * 2)              // 18432
#define BBYT  (64 * 136 * 2)              // 17408
#define GSTGB (ABYT + BBYT)               // 35840 per stage
#define STG_STRIDE 132
#define GEMM_SMEM (3 * GSTGB)             // 107520 (> 128*132*4 = 67584 staging)

__device__ __forceinline__ void gemm_mainloop(
    uint32_t sbase, int tid, int lane, int wm, int wn, int brow, int bcol,
    const __half* __restrict__ A, const __half* __restrict__ B,
    int Ncols, int K, float acc[4][8][4])
{
#pragma unroll
    for (int mt = 0; mt < 4; mt++)
#pragma unroll
        for (int nt = 0; nt < 8; nt++)
#pragma unroll
            for (int r = 0; r < 4; r++) acc[mt][nt][r] = 0.f;

    const int nIter = K / 64;

    auto issue = [&](int it, int s) {
        const int k0 = it * 64;
        uint32_t ab = sbase + (uint32_t)(s * GSTGB);
        uint32_t bb = ab + ABYT;
        // A: 128 rows x 64 halfs = 1024 x 8-half chunks
#pragma unroll
        for (int i = 0; i < 8; i++) {
            int f = tid + i * 128;
            int m = f >> 3, c = (f & 7) * 8;
            cpa16(ab + (uint32_t)(m * 72 + c) * 2, A + (size_t)(brow + m) * K + k0 + c);
        }
        // B: 64 rows x 128 cols = 1024 x 8-half chunks
#pragma unroll
        for (int i = 0; i < 8; i++) {
            int f = tid + i * 128;
            int kr = f >> 4, nc = (f & 15) * 8;
            cpa16(bb + (uint32_t)(kr * 136 + nc) * 2, B + (size_t)(k0 + kr) * Ncols + bcol + nc);
        }
        asm volatile("cp.async.commit_group;");
    };

    issue(0, 0);
    issue(1, 1);

    const int dofb = (lane >> 4) * 8;
    const int srb  = ((lane >> 3) & 1) * 8 + (lane & 7);

    for (int it = 0; it < nIter; ++it) {
        if (it < nIter - 1) asm volatile("cp.async.wait_group 1;" ::: "memory");
        else                asm volatile("cp.async.wait_group 0;" ::: "memory");
        __syncthreads();
        if (it + 2 < nIter) issue(it + 2, (it + 2) % 3);

        uint32_t ab = sbase + (uint32_t)((it % 3) * GSTGB);
        uint32_t bb = ab + ABYT;
#pragma unroll
        for (int ks = 0; ks < 4; ks++) {
            const int koff = ks * 16;
            uint32_t a[4][4];
#pragma unroll
            for (int mt = 0; mt < 4; mt++)
                ldm4(a[mt], ab + (uint32_t)((wm*64 + mt*16 + (lane & 15)) * 72
                                            + koff + dofb) * 2);
#pragma unroll
            for (int db = 0; db < 4; db++) {
                uint32_t bv[4];
                ldm4t(bv, bb + (uint32_t)((koff + srb) * 136
                                          + wn*64 + db*16 + dofb) * 2);
#pragma unroll
                for (int mt = 0; mt < 4; mt++) {
                    mma16(acc[mt][db*2+0], a[mt], bv[0], bv[1]);
                    mma16(acc[mt][db*2+1], a[mt], bv[2], bv[3]);
                }
            }
        }
    }
}

// ---- fused QKV projection with in-epilogue RoPE ----
__global__ __launch_bounds__(128, 2)
void gemm_qkv(const __half* __restrict__ A,
              const float* __restrict__ qb, const float* __restrict__ kb,
              const float* __restrict__ vb,
              const float* __restrict__ sinp, const float* __restrict__ cosp)
{
    extern __shared__ __half smh[];
    const uint32_t sbase = (uint32_t)__cvta_generic_to_shared(smh);
    const int tid = threadIdx.x, lane = tid & 31;
    const int w = tid >> 5, wm = w >> 1, wn = w & 1;
    const int brow = blockIdx.x * 128;
    const int by = blockIdx.y;

    const __half* B;
    int bcol, Ncols, mode;
    if (by < 28)      { B = g_wqh; bcol = by * 128;        Ncols = QCOLS; mode = 0; }
    else if (by < 32) { B = g_wkh; bcol = (by - 28) * 128; Ncols = KCOLS; mode = 1; }
    else              { B = g_wvh; bcol = (by - 32) * 128; Ncols = KCOLS; mode = 2; }

    float acc[4][8][4];
    gemm_mainloop(sbase, tid, lane, wm, wn, brow, bcol, A, B, Ncols, D_DIM, acc);

    const int g = lane >> 2, t2 = (lane & 3) * 2;
    const float* bias = (mode == 0) ? qb : (mode == 1) ? kb : vb;

    if (mode == 2) {        // V -> g_vh fp16 (fp32 acc+bias, then rn)
#pragma unroll
        for (int mt = 0; mt < 4; mt++) {
            int row0 = brow + wm*64 + mt*16 + g;
#pragma unroll
            for (int nt = 0; nt < 8; nt++) {
                int col = bcol + wn*64 + nt*8 + t2;
                float b0 = bias[col], b1 = bias[col + 1];
                *(__half2*)(g_vh + (size_t)row0 * KCOLS + col) =
                    __floats2half2_rn(acc[mt][nt][0] + b0, acc[mt][nt][1] + b1);
                *(__half2*)(g_vh + (size_t)(row0 + 8) * KCOLS + col) =
                    __floats2half2_rn(acc[mt][nt][2] + b0, acc[mt][nt][3] + b1);
            }
        }
        return;
    }

    // ---- Q/K: stage fp32 acc+bias in smem, then rope -> fp16 ----
    float* stg = (float*)smh;
    __syncthreads();
#pragma unroll
    for (int mt = 0; mt < 4; mt++) {
        int rl0 = wm*64 + mt*16 + g;
#pragma unroll
        for (int nt = 0; nt < 8; nt++) {
            int cl = wn*64 + nt*8 + t2;
            float b0 = bias[bcol + cl], b1 = bias[bcol + cl + 1];
            *(float2*)(stg + rl0 * STG_STRIDE + cl) =
                make_float2(acc[mt][nt][0] + b0, acc[mt][nt][1] + b1);
            *(float2*)(stg + (rl0 + 8) * STG_STRIDE + cl) =
                make_float2(acc[mt][nt][2] + b0, acc[mt][nt][3] + b1);
        }
    }
    __syncthreads();

    __half* dst = (mode == 0) ? g_qh : g_kh;
    const float scale = (mode == 0) ? SCALE_ATTN : 1.0f;
    const int cpair = (tid & 31) * 2;
    const int rsub  = tid >> 5;
#pragma unroll 4
    for (int step = 0; step < 32; ++step) {
        int rl = step * 4 + rsub;
        int t  = brow + rl;
        float x1a = stg[rl * STG_STRIDE + cpair];
        float x1b = stg[rl * STG_STRIDE + cpair + 1];
        float x2a = stg[rl * STG_STRIDE + cpair + 64];
        float x2b = stg[rl * STG_STRIDE + cpair + 65];
        float2 sv = *(const float2*)(sinp + t * 64 + cpair);
        float2 cv = *(const float2*)(cosp + t * 64 + cpair);
        *(__half2*)(dst + (size_t)t * Ncols + bcol + cpair) =
            __floats2half2_rn((x1a * cv.x - x2a * sv.x) * scale,
                              (x1b * cv.y - x2b * sv.y) * scale);
        *(__half2*)(dst + (size_t)t * Ncols + bcol + cpair + 64) =
            __floats2half2_rn((x2a * cv.x + x1a * sv.x) * scale,
                              (x2b * cv.y + x1b * sv.y) * scale);
    }
}

// ---- O-projection: fp32 out, no bias ----
__global__ __launch_bounds__(128, 2)
void gemm_h(const __half* __restrict__ A, const __half* __restrict__ B,
            float* __restrict__ C, int Ncols, int K)
{
    extern __shared__ __half smh[];
    const uint32_t sbase = (uint32_t)__cvta_generic_to_shared(smh);
    const int tid = threadIdx.x, lane = tid & 31;
    const int w = tid >> 5, wm = w >> 1, wn = w & 1;
    const int brow = blockIdx.x * 128, bcol = blockIdx.y * 128;

    float acc[4][8][4];
    gemm_mainloop(sbase, tid, lane, wm, wn, brow, bcol, A, B, Ncols, K, acc);

    const int g = lane >> 2, t2 = (lane & 3) * 2;
#pragma unroll
    for (int mt = 0; mt < 4; mt++) {
        int row0 = brow + wm*64 + mt*16 + g;
#pragma unroll
        for (int nt = 0; nt < 8; nt++) {
            int col = bcol + wn*64 + nt*8 + t2;
            *(float2*)(C + (size_t)row0 * Ncols + col) =
                make_float2(acc[mt][nt][0], acc[mt][nt][1]);
            *(float2*)(C + (size_t)(row0 + 8) * Ncols + col) =
                make_float2(acc[mt][nt][2], acc[mt][nt][3]);
        }
    }
}

// =====================================================================
// fp16 flash attention.  BM=128, BN=64, 8 warps; Q + P in registers;
// K ldmatrix, V ldmatrix.trans; K/V 3-stage cp.async; heavy blocks first.
// grid = (T/128, NHEADS)
// =====================================================================
#define QBYTES  (128 * 136 * 2)     // 34816
#define KVSTG   (2 * 64 * 136 * 2)  // 34816
#define FLASH_SMEM (QBYTES + 3 * KVSTG)   // 139264

__global__ __launch_bounds__(256, 1)
void flash_h_kernel()
{
    extern __shared__ __half smf[];
    const uint32_t sbase = (uint32_t)__cvta_generic_to_shared(smf);
    const int br = gridDim.x - 1 - blockIdx.x;   // heavy blocks first
    const int n = blockIdx.y, kh = n / GRP;
    const int tid = threadIdx.x, lane = tid & 31;
    const int g = lane >> 2, t2 = (lane & 3) * 2;
    const int w = tid >> 5, rowbase = w * 16;

    auto issue_kv = [&](int j, int s) {
        const __half* Kg = g_kh + (size_t)(j * 64) * KCOLS + kh * HD;
        const __half* Vg = g_vh + (size_t)(j * 64) * KCOLS + kh * HD;
        uint32_t Kb = sbase + QBYTES + (uint32_t)(s * KVSTG);
        uint32_t Vb = Kb + 64 * 136 * 2;
#pragma unroll
        for (int i = 0; i < 4; i++) {
            int f = tid + i * 256;
            int r = f >> 4, c = (f & 15) * 8;
            cpa16(Kb + (uint32_t)(r * 136 + c) * 2, Kg + (size_t)r * KCOLS + c);
        }
#pragma unroll
        for (int i = 0; i < 4; i++) {
            int f = tid + i * 256;
            int r = f >> 4, c = (f & 15) * 8;
            cpa16(Vb + (uint32_t)(r * 136 + c) * 2, Vg + (size_t)r * KCOLS + c);
        }
        asm volatile("cp.async.commit_group;");
    };

    const int jmax = 2 * br + 1;

    {
        const __half* Qg = g_qh + (size_t)(br * 128) * QCOLS + n * HD;
#pragma unroll
        for (int i = 0; i < 8; i++) {
            int f = tid + i * 256;
            int r = f >> 4, c = (f & 15) * 8;
            cpa16(sbase + (uint32_t)(r * 136 + c) * 2, Qg + (size_t)r * QCOLS + c);
        }
        asm volatile("cp.async.commit_group;");
    }
    issue_kv(0, 0);
    issue_kv(1, 1);
    asm volatile("cp.async.wait_group 2;" ::: "memory");
    __syncthreads();

    uint32_t qf[8][4];
#pragma unroll
    for (int kk = 0; kk < 8; kk++)
        ldm4(qf[kk], sbase + (uint32_t)((rowbase + (lane & 15)) * 136
                                        + kk * 16 + (lane >> 4) * 8) * 2);

    float m0 = -1e30f, m1 = -1e30f, l0 = 0.f, l1 = 0.f;
    float acc[16][4];
#pragma unroll
    for (int nt = 0; nt < 16; nt++)
#pragma unroll
        for (int r = 0; r < 4; r++) acc[nt][r] = 0.f;

    for (int j = 0; j <= jmax; ++j) {
        if (j < jmax) asm volatile("cp.async.wait_group 1;" ::: "memory");
        else          asm volatile("cp.async.wait_group 0;" ::: "memory");
        __syncthreads();
        if (j + 2 <= jmax) issue_kv(j + 2, (j + 2) % 3);

        uint32_t Kb = sbase + QBYTES + (uint32_t)((j % 3) * KVSTG);
        uint32_t Vb = Kb + 64 * 136 * 2;

        float s_acc[8][4];
#pragma unroll
        for (int nt = 0; nt < 8; nt++)
#pragma unroll
            for (int r = 0; r < 4; r++) s_acc[nt][r] = 0.f;

#pragma unroll
        for (int kk = 0; kk < 8; kk++) {
            const int koff = kk * 16 + (lane >> 4) * 8;
#pragma unroll
            for (int nb = 0; nb < 4; nb++) {
                uint32_t bk[4];
                ldm4(bk, Kb + (uint32_t)((nb*16 + (lane & 15)) * 136 + koff) * 2);
                mma16(s_acc[nb*2+0], qf[kk], bk[0], bk[2]);
                mma16(s_acc[nb*2+1], qf[kk], bk[1], bk[3]);
            }
        }

        if (j >= 2 * br) {
            int q0r = br * 128 + rowbase + g;
            int q1r = q0r + 8;
            int kb0 = j * 64;
#pragma unroll
            for (int nt = 0; nt < 8; nt++) {
                int c0 = kb0 + nt * 8 + t2, c1 = c0 + 1;
                if (c0 > q0r) s_acc[nt][0] = -1e30f;
                if (c1 > q0r) s_acc[nt][1] = -1e30f;
                if (c0 > q1r) s_acc[nt][2] = -1e30f;
                if (c1 > q1r) s_acc[nt][3] = -1e30f;
            }
        }

        float rmax0 = -1e30f, rmax1 = -1e30f;
#pragma unroll
        for (int nt = 0; nt < 8; nt++) {
            rmax0 = fmaxf(rmax0, fmaxf(s_acc[nt][0], s_acc[nt][1]));
            rmax1 = fmaxf(rmax1, fmaxf(s_acc[nt][2], s_acc[nt][3]));
        }
        rmax0 = fmaxf(rmax0, __shfl_xor_sync(0xffffffffu, rmax0, 1));
        rmax0 = fmaxf(rmax0, __shfl_xor_sync(0xffffffffu, rmax0, 2));
        rmax1 = fmaxf(rmax1, __shfl_xor_sync(0xffffffffu, rmax1, 1));
        rmax1 = fmaxf(rmax1, __shfl_xor_sync(0xffffffffu, rmax1, 2));
        float mn0 = fmaxf(m0, rmax0), mn1 = fmaxf(m1, rmax1);
        float alpha0 = __expf(m0 - mn0), alpha1 = __expf(m1 - mn1);

        uint32_t pa[4][4];
        float sum0 = 0.f, sum1 = 0.f;
#pragma unroll
        for (int nt = 0; nt < 8; nt++) {
            float e0 = __expf(s_acc[nt][0] - mn0);
            float e1 = __expf(s_acc[nt][1] - mn0);
            float e2 = __expf(s_acc[nt][2] - mn1);
            float e3 = __expf(s_acc[nt][3] - mn1);
            sum0 += e0 + e1;  sum1 += e2 + e3;
            const int kk2 = nt >> 1, hi = (nt & 1) * 2;
            pa[kk2][hi + 0] = h2u(e0, e1);
            pa[kk2][hi + 1] = h2u(e2, e3);
        }
        sum0 += __shfl_xor_sync(0xffffffffu, sum0, 1);
        sum0 += __shfl_xor_sync(0xffffffffu, sum0, 2);
        sum1 += __shfl_xor_sync(0xffffffffu, sum1, 1);
        sum1 += __shfl_xor_sync(0xffffffffu, sum1, 2);
        l0 = l0 * alpha0 + sum0;  m0 = mn0;
        l1 = l1 * alpha1 + sum1;  m1 = mn1;
#pragma unroll
        for (int nt = 0; nt < 16; nt++) {
            acc[nt][0] *= alpha0;  acc[nt][1] *= alpha0;
            acc[nt][2] *= alpha1;  acc[nt][3] *= alpha1;
        }

#pragma unroll
        for (int kk2 = 0; kk2 < 4; kk2++) {
            const int srow = kk2 * 16 + ((lane >> 3) & 1) * 8 + (lane & 7);
            const int dofb = (lane >> 4) * 8;
#pragma unroll
            for (int db = 0; db < 8; db++) {
                uint32_t bv[4];
                ldm4t(bv, Vb + (uint32_t)(srow * 136 + db * 16 + dofb) * 2);
                mma16(acc[db*2+0], pa[kk2], bv[0], bv[1]);
                mma16(acc[db*2+1], pa[kk2], bv[2], bv[3]);
            }
        }
    }

    float rl0 = 1.f / l0, rl1 = 1.f / l1;
    int row0 = br * 128 + rowbase + g;
    __half* op0 = g_aoh + (size_t)row0 * QCOLS + n * HD;
    __half* op1 = op0 + (size_t)8 * QCOLS;
#pragma unroll
    for (int nt = 0; nt < 16; nt++) {
        int col = nt * 8 + t2;
        *(__half2*)(op0 + col) = __floats2half2_rn(acc[nt][0] * rl0, acc[nt][1] * rl0);
        *(__half2*)(op1 + col) = __floats2half2_rn(acc[nt][2] * rl1, acc[nt][3] * rl1);
    }
}

// =====================================================================
extern "C" void kernel_launch(void* const* d_in, const int* in_sizes, int n_in,
                              void* d_out, int out_size)
{
    const float* x    = (const float*)d_in[0];
    const float* sinp = (const float*)d_in[2];
    const float* cosp = (const float*)d_in[3];
    const float* wq   = (const float*)d_in[4];
    const float* wk   = (const float*)d_in[5];
    const float* wv   = (const float*)d_in[6];
    const float* wo   = (const float*)d_in[7];
    const float* qb   = (const float*)d_in[8];
    const float* kb   = (const float*)d_in[9];
    const float* vb   = (const float*)d_in[10];
    float* out = (float*)d_out;

    __half *xh, *woh, *aoh;
    cudaGetSymbolAddress((void**)&xh,  g_xh);
    cudaGetSymbolAddress((void**)&woh, g_woh);
    cudaGetSymbolAddress((void**)&aoh, g_aoh);

    cudaFuncSetAttribute(gemm_qkv,
                         cudaFuncAttributeMaxDynamicSharedMemorySize, GEMM_SMEM);
    cudaFuncSetAttribute(gemm_h,
                         cudaFuncAttributeMaxDynamicSharedMemorySize, GEMM_SMEM);
    cudaFuncSetAttribute(flash_h_kernel,
                         cudaFuncAttributeMaxDynamicSharedMemorySize, FLASH_SMEM);

    // ---- merged prepass: all fp16 conversions in one launch ----
    cvt_all_kernel<<<(SEGT + 255)/256, 256>>>(x, wq, wk, wv, wo);

    // ---- fused QKV projection + RoPE ----
    gemm_qkv<<<dim3(T_LEN/128, 36), 128, GEMM_SMEM>>>(xh, qb, kb, vb, sinp, cosp);

    // ---- flash attention (heavy blocks first) ----
    flash_h_kernel<<<dim3(T_LEN/128, NHEADS), 256, FLASH_SMEM>>>();

    // ---- output projection -> d_out ----
    gemm_h<<<dim3(T_LEN/128, D_DIM/128), 128, GEMM_SMEM>>>(aoh, woh, out, D_DIM, QCOLS);
}

// round 17
// speedup vs baseline: 1.0736x; 1.0736x over previous
#include <cuda_runtime.h>
#include <cuda_fp16.h>
#include <cstddef>
#include <cstdint>

#define T_LEN   2048
#define D_DIM   3584
#define NHEADS  28
#define KVH     4
#define HD      128
#define GRP     7
#define QCOLS   (NHEADS*HD)   // 3584
#define KCOLS   (KVH*HD)      // 512
#define SCALE_ATTN 0.08838834764831845f

// -------- scratch (no cudaMalloc allowed) --------
__device__ __half g_xh [T_LEN * D_DIM];          // x fp16
__device__ __half g_wqh[D_DIM * QCOLS];          // wq fp16 (K-major natural layout)
__device__ __half g_wkh[D_DIM * KCOLS];
__device__ __half g_wvh[D_DIM * KCOLS];
__device__ __half g_woh[QCOLS * D_DIM];          // wo fp16 [nh][d]
__device__ __half g_qh [T_LEN * QCOLS];          // rope(Q)*scale fp16
__device__ __half g_kh [T_LEN * KCOLS];          // rope(K) fp16
__device__ __half g_vh [T_LEN * KCOLS];          // V fp16
__device__ __half g_aoh[T_LEN * QCOLS];          // attention out fp16

// ---------------- helpers ----------------
__device__ __forceinline__ void cpa16(uint32_t dst, const void* src) {
    asm volatile("cp.async.cg.shared.global [%0], [%1], 16;" :: "r"(dst), "l"(src));
}
__device__ __forceinline__ void ldm4(uint32_t* r, uint32_t a) {
    asm volatile("ldmatrix.sync.aligned.m8n8.x4.shared.b16 {%0,%1,%2,%3}, [%4];"
                 : "=r"(r[0]), "=r"(r[1]), "=r"(r[2]), "=r"(r[3]) : "r"(a));
}
__device__ __forceinline__ void ldm4t(uint32_t* r, uint32_t a) {
    asm volatile("ldmatrix.sync.aligned.m8n8.x4.trans.shared.b16 {%0,%1,%2,%3}, [%4];"
                 : "=r"(r[0]), "=r"(r[1]), "=r"(r[2]), "=r"(r[3]) : "r"(a));
}
__device__ __forceinline__ void mma16(float* c, const uint32_t* a, uint32_t b0, uint32_t b1) {
    asm volatile(
        "mma.sync.aligned.m16n8k16.row.col.f32.f16.f16.f32 "
        "{%0,%1,%2,%3}, {%4,%5,%6,%7}, {%8,%9}, {%0,%1,%2,%3};"
        : "+f"(c[0]), "+f"(c[1]), "+f"(c[2]), "+f"(c[3])
        : "r"(a[0]), "r"(a[1]), "r"(a[2]), "r"(a[3]), "r"(b0), "r"(b1));
}
__device__ __forceinline__ uint32_t h2u(float a, float b) {
    __half2 h = __floats2half2_rn(a, b);
    return *reinterpret_cast<uint32_t*>(&h);
}

// =====================================================================
// merged prepass: all 5 fp32->fp16 conversions in ONE launch
// =====================================================================
#define N4_X   (T_LEN*D_DIM/4)
#define N4_WQ  (D_DIM*QCOLS/4)
#define N4_WK  (D_DIM*KCOLS/4)
#define N4_WO  (QCOLS*D_DIM/4)
#define SEG0   N4_X
#define SEG1   (SEG0 + N4_WQ)
#define SEG2   (SEG1 + N4_WK)
#define SEG3   (SEG2 + N4_WK)
#define SEGT   (SEG3 + N4_WO)

__global__ __launch_bounds__(256)
void cvt_all_kernel(const float* __restrict__ x,  const float* __restrict__ wq,
                    const float* __restrict__ wk, const float* __restrict__ wv,
                    const float* __restrict__ wo)
{
    int i = blockIdx.x * blockDim.x + threadIdx.x;
    if (i >= SEGT) return;
    const float* s; __half* d; int off;
    if (i < SEG0)      { s = x;  d = g_xh;  off = i; }
    else if (i < SEG1) { s = wq; d = g_wqh; off = i - SEG0; }
    else if (i < SEG2) { s = wk; d = g_wkh; off = i - SEG1; }
    else if (i < SEG3) { s = wv; d = g_wvh; off = i - SEG2; }
    else               { s = wo; d = g_woh; off = i - SEG3; }
    float4 v = ((const float4*)s)[off];
    ((__half2*)d)[2*off]   = __floats2half2_rn(v.x, v.y);
    ((__half2*)d)[2*off+1] = __floats2half2_rn(v.z, v.w);
}

// =====================================================================
// QKV GEMM mainloop (proven R15 config): CTA 128x128, BK=32, 3-stage
// cp.async, 128 threads, 4 warps (2x2), warp tile 64x64.
// =====================================================================
#define ABYT 10240                        // A: 128 x 40 halfs x 2B
#define GSTGB (ABYT + 32*136*2)           // 18944 per stage
#define STG_STRIDE 132
#define GEMM_SMEM (128 * STG_STRIDE * 4)  // 67584 >= 3*GSTGB (56832); epilogue staging

__device__ __forceinline__ void gemm_mainloop(
    uint32_t sbase, int tid, int lane, int wm, int wn, int brow, int bcol,
    const __half* __restrict__ A, const __half* __restrict__ B,
    int Ncols, int K, float acc[4][8][4])
{
#pragma unroll
    for (int mt = 0; mt < 4; mt++)
#pragma unroll
        for (int nt = 0; nt < 8; nt++)
#pragma unroll
            for (int r = 0; r < 4; r++) acc[mt][nt][r] = 0.f;

    const int nIter = K / 32;

    auto issue = [&](int it, int s) {
        const int k0 = it * 32;
        uint32_t ab = sbase + (uint32_t)(s * GSTGB);
        uint32_t bb = ab + ABYT;
#pragma unroll
        for (int i = 0; i < 4; i++) {
            int f = tid + i * 128;
            int m = f >> 2, c = (f & 3) * 8;
            cpa16(ab + (uint32_t)(m * 40 + c) * 2, A + (size_t)(brow + m) * K + k0 + c);
        }
#pragma unroll
        for (int i = 0; i < 4; i++) {
            int f = tid + i * 128;
            int kr = f >> 4, nc = (f & 15) * 8;
            cpa16(bb + (uint32_t)(kr * 136 + nc) * 2, B + (size_t)(k0 + kr) * Ncols + bcol + nc);
        }
        asm volatile("cp.async.commit_group;");
    };

    issue(0, 0);
    issue(1, 1);

    const int dofb = (lane >> 4) * 8;
    const int srb  = ((lane >> 3) & 1) * 8 + (lane & 7);

    for (int it = 0; it < nIter; ++it) {
        if (it < nIter - 1) asm volatile("cp.async.wait_group 1;" ::: "memory");
        else                asm volatile("cp.async.wait_group 0;" ::: "memory");
        __syncthreads();
        if (it + 2 < nIter) issue(it + 2, (it + 2) % 3);

        uint32_t ab = sbase + (uint32_t)((it % 3) * GSTGB);
        uint32_t bb = ab + ABYT;
#pragma unroll
        for (int ks = 0; ks < 2; ks++) {
            const int koff = ks * 16;
            uint32_t a[4][4];
#pragma unroll
            for (int mt = 0; mt < 4; mt++)
                ldm4(a[mt], ab + (uint32_t)((wm*64 + mt*16 + (lane & 15)) * 40
                                            + koff + dofb) * 2);
#pragma unroll
            for (int db = 0; db < 4; db++) {
                uint32_t bv[4];
                ldm4t(bv, bb + (uint32_t)((koff + srb) * 136
                                          + wn*64 + db*16 + dofb) * 2);
#pragma unroll
                for (int mt = 0; mt < 4; mt++) {
                    mma16(acc[mt][db*2+0], a[mt], bv[0], bv[1]);
                    mma16(acc[mt][db*2+1], a[mt], bv[2], bv[3]);
                }
            }
        }
    }
}

// ---- fused QKV projection with in-epilogue RoPE (unchanged from best) ----
__global__ __launch_bounds__(128, 2)
void gemm_qkv(const __half* __restrict__ A,
              const float* __restrict__ qb, const float* __restrict__ kb,
              const float* __restrict__ vb,
              const float* __restrict__ sinp, const float* __restrict__ cosp)
{
    extern __shared__ __half smh[];
    const uint32_t sbase = (uint32_t)__cvta_generic_to_shared(smh);
    const int tid = threadIdx.x, lane = tid & 31;
    const int w = tid >> 5, wm = w >> 1, wn = w & 1;
    const int brow = blockIdx.x * 128;
    const int by = blockIdx.y;

    const __half* B;
    int bcol, Ncols, mode;
    if (by < 28)      { B = g_wqh; bcol = by * 128;        Ncols = QCOLS; mode = 0; }
    else if (by < 32) { B = g_wkh; bcol = (by - 28) * 128; Ncols = KCOLS; mode = 1; }
    else              { B = g_wvh; bcol = (by - 32) * 128; Ncols = KCOLS; mode = 2; }

    float acc[4][8][4];
    gemm_mainloop(sbase, tid, lane, wm, wn, brow, bcol, A, B, Ncols, D_DIM, acc);

    const int g = lane >> 2, t2 = (lane & 3) * 2;
    const float* bias = (mode == 0) ? qb : (mode == 1) ? kb : vb;

    if (mode == 2) {        // V -> g_vh fp16 (fp32 acc+bias, then rn)
#pragma unroll
        for (int mt = 0; mt < 4; mt++) {
            int row0 = brow + wm*64 + mt*16 + g;
#pragma unroll
            for (int nt = 0; nt < 8; nt++) {
                int col = bcol + wn*64 + nt*8 + t2;
                float b0 = bias[col], b1 = bias[col + 1];
                *(__half2*)(g_vh + (size_t)row0 * KCOLS + col) =
                    __floats2half2_rn(acc[mt][nt][0] + b0, acc[mt][nt][1] + b1);
                *(__half2*)(g_vh + (size_t)(row0 + 8) * KCOLS + col) =
                    __floats2half2_rn(acc[mt][nt][2] + b0, acc[mt][nt][3] + b1);
            }
        }
        return;
    }

    // ---- Q/K: stage fp32 acc+bias in smem, then rope -> fp16 ----
    float* stg = (float*)smh;
    __syncthreads();
#pragma unroll
    for (int mt = 0; mt < 4; mt++) {
        int rl0 = wm*64 + mt*16 + g;
#pragma unroll
        for (int nt = 0; nt < 8; nt++) {
            int cl = wn*64 + nt*8 + t2;
            float b0 = bias[bcol + cl], b1 = bias[bcol + cl + 1];
            *(float2*)(stg + rl0 * STG_STRIDE + cl) =
                make_float2(acc[mt][nt][0] + b0, acc[mt][nt][1] + b1);
            *(float2*)(stg + (rl0 + 8) * STG_STRIDE + cl) =
                make_float2(acc[mt][nt][2] + b0, acc[mt][nt][3] + b1);
        }
    }
    __syncthreads();

    __half* dst = (mode == 0) ? g_qh : g_kh;
    const float scale = (mode == 0) ? SCALE_ATTN : 1.0f;
    const int cpair = (tid & 31) * 2;
    const int rsub  = tid >> 5;
#pragma unroll 4
    for (int step = 0; step < 32; ++step) {
        int rl = step * 4 + rsub;
        int t  = brow + rl;
        float x1a = stg[rl * STG_STRIDE + cpair];
        float x1b = stg[rl * STG_STRIDE + cpair + 1];
        float x2a = stg[rl * STG_STRIDE + cpair + 64];
        float x2b = stg[rl * STG_STRIDE + cpair + 65];
        float2 sv = *(const float2*)(sinp + t * 64 + cpair);
        float2 cv = *(const float2*)(cosp + t * 64 + cpair);
        *(__half2*)(dst + (size_t)t * Ncols + bcol + cpair) =
            __floats2half2_rn((x1a * cv.x - x2a * sv.x) * scale,
                              (x1b * cv.y - x2b * sv.y) * scale);
        *(__half2*)(dst + (size_t)t * Ncols + bcol + cpair + 64) =
            __floats2half2_rn((x2a * cv.x + x1a * sv.x) * scale,
                              (x2b * cv.y + x1b * sv.y) * scale);
    }
}

// =====================================================================
// O-projection: CTA tile 128x64 (896 CTAs -> 2.02 even waves),
// warp tile 64x32, 128 thr, 3 CTAs/SM (12 warps).  BK=32, 3-stage.
// =====================================================================
#define H_ABYT (128 * 40 * 2)             // 10240
#define H_BBYT (32 * 72 * 2)              // 4608
#define H_STG  (H_ABYT + H_BBYT)          // 14848
#define H_SMEM (3 * H_STG)                // 44544

__global__ __launch_bounds__(128, 3)
void gemm_h64(const __half* __restrict__ A, const __half* __restrict__ B,
              float* __restrict__ C, int Ncols, int K)
{
    extern __shared__ __half smh[];
    const uint32_t sbase = (uint32_t)__cvta_generic_to_shared(smh);
    const int tid = threadIdx.x, lane = tid & 31;
    const int w = tid >> 5, wm = w >> 1, wn = w & 1;
    const int brow = blockIdx.x * 128, bcol = blockIdx.y * 64;

    float acc[4][4][4];
#pragma unroll
    for (int mt = 0; mt < 4; mt++)
#pragma unroll
        for (int nt = 0; nt < 4; nt++)
#pragma unroll
            for (int r = 0; r < 4; r++) acc[mt][nt][r] = 0.f;

    const int nIter = K / 32;

    auto issue = [&](int it, int s) {
        const int k0 = it * 32;
        uint32_t ab = sbase + (uint32_t)(s * H_STG);
        uint32_t bb = ab + H_ABYT;
#pragma unroll
        for (int i = 0; i < 4; i++) {
            int f = tid + i * 128;
            int m = f >> 2, c = (f & 3) * 8;
            cpa16(ab + (uint32_t)(m * 40 + c) * 2, A + (size_t)(brow + m) * K + k0 + c);
        }
#pragma unroll
        for (int i = 0; i < 2; i++) {
            int f = tid + i * 128;             // 0..255
            int kr = f >> 3, nc = (f & 7) * 8;
            cpa16(bb + (uint32_t)(kr * 72 + nc) * 2, B + (size_t)(k0 + kr) * Ncols + bcol + nc);
        }
        asm volatile("cp.async.commit_group;");
    };

    issue(0, 0);
    issue(1, 1);

    const int dofb = (lane >> 4) * 8;
    const int srb  = ((lane >> 3) & 1) * 8 + (lane & 7);

    for (int it = 0; it < nIter; ++it) {
        if (it < nIter - 1) asm volatile("cp.async.wait_group 1;" ::: "memory");
        else                asm volatile("cp.async.wait_group 0;" ::: "memory");
        __syncthreads();
        if (it + 2 < nIter) issue(it + 2, (it + 2) % 3);

        uint32_t ab = sbase + (uint32_t)((it % 3) * H_STG);
        uint32_t bb = ab + H_ABYT;
#pragma unroll
        for (int ks = 0; ks < 2; ks++) {
            const int koff = ks * 16;
            uint32_t a[4][4];
#pragma unroll
            for (int mt = 0; mt < 4; mt++)
                ldm4(a[mt], ab + (uint32_t)((wm*64 + mt*16 + (lane & 15)) * 40
                                            + koff + dofb) * 2);
#pragma unroll
            for (int db = 0; db < 2; db++) {
                uint32_t bv[4];
                ldm4t(bv, bb + (uint32_t)((koff + srb) * 72
                                          + wn*32 + db*16 + dofb) * 2);
#pragma unroll
                for (int mt = 0; mt < 4; mt++) {
                    mma16(acc[mt][db*2+0], a[mt], bv[0], bv[1]);
                    mma16(acc[mt][db*2+1], a[mt], bv[2], bv[3]);
                }
            }
        }
    }

    const int g = lane >> 2, t2 = (lane & 3) * 2;
#pragma unroll
    for (int mt = 0; mt < 4; mt++) {
        int row0 = brow + wm*64 + mt*16 + g;
#pragma unroll
        for (int nt = 0; nt < 4; nt++) {
            int col = bcol + wn*32 + nt*8 + t2;
            *(float2*)(C + (size_t)row0 * Ncols + col) =
                make_float2(acc[mt][nt][0], acc[mt][nt][1]);
            *(float2*)(C + (size_t)(row0 + 8) * Ncols + col) =
                make_float2(acc[mt][nt][2], acc[mt][nt][3]);
        }
    }
}

// =====================================================================
// fp16 flash attention (unchanged from best).  BM=128, BN=64, 8 warps;
// Q + P in registers; K ldmatrix, V ldmatrix.trans; 3-stage cp.async.
// grid = (T/128, NHEADS)
// =====================================================================
#define QBYTES  (128 * 136 * 2)     // 34816
#define KVSTG   (2 * 64 * 136 * 2)  // 34816
#define FLASH_SMEM (QBYTES + 3 * KVSTG)   // 139264

__global__ __launch_bounds__(256, 1)
void flash_h_kernel()
{
    extern __shared__ __half smf[];
    const uint32_t sbase = (uint32_t)__cvta_generic_to_shared(smf);
    const int br = gridDim.x - 1 - blockIdx.x;   // heavy blocks first
    const int n = blockIdx.y, kh = n / GRP;
    const int tid = threadIdx.x, lane = tid & 31;
    const int g = lane >> 2, t2 = (lane & 3) * 2;
    const int w = tid >> 5, rowbase = w * 16;

    auto issue_kv = [&](int j, int s) {
        const __half* Kg = g_kh + (size_t)(j * 64) * KCOLS + kh * HD;
        const __half* Vg = g_vh + (size_t)(j * 64) * KCOLS + kh * HD;
        uint32_t Kb = sbase + QBYTES + (uint32_t)(s * KVSTG);
        uint32_t Vb = Kb + 64 * 136 * 2;
#pragma unroll
        for (int i = 0; i < 4; i++) {
            int f = tid + i * 256;
            int r = f >> 4, c = (f & 15) * 8;
            cpa16(Kb + (uint32_t)(r * 136 + c) * 2, Kg + (size_t)r * KCOLS + c);
        }
#pragma unroll
        for (int i = 0; i < 4; i++) {
            int f = tid + i * 256;
            int r = f >> 4, c = (f & 15) * 8;
            cpa16(Vb + (uint32_t)(r * 136 + c) * 2, Vg + (size_t)r * KCOLS + c);
        }
        asm volatile("cp.async.commit_group;");
    };

    const int jmax = 2 * br + 1;

    {
        const __half* Qg = g_qh + (size_t)(br * 128) * QCOLS + n * HD;
#pragma unroll
        for (int i = 0; i < 8; i++) {
            int f = tid + i * 256;
            int r = f >> 4, c = (f & 15) * 8;
            cpa16(sbase + (uint32_t)(r * 136 + c) * 2, Qg + (size_t)r * QCOLS + c);
        }
        asm volatile("cp.async.commit_group;");
    }
    issue_kv(0, 0);
    issue_kv(1, 1);
    asm volatile("cp.async.wait_group 2;" ::: "memory");
    __syncthreads();

    uint32_t qf[8][4];
#pragma unroll
    for (int kk = 0; kk < 8; kk++)
        ldm4(qf[kk], sbase + (uint32_t)((rowbase + (lane & 15)) * 136
                                        + kk * 16 + (lane >> 4) * 8) * 2);

    float m0 = -1e30f, m1 = -1e30f, l0 = 0.f, l1 = 0.f;
    float acc[16][4];
#pragma unroll
    for (int nt = 0; nt < 16; nt++)
#pragma unroll
        for (int r = 0; r < 4; r++) acc[nt][r] = 0.f;

    for (int j = 0; j <= jmax; ++j) {
        if (j < jmax) asm volatile("cp.async.wait_group 1;" ::: "memory");
        else          asm volatile("cp.async.wait_group 0;" ::: "memory");
        __syncthreads();
        if (j + 2 <= jmax) issue_kv(j + 2, (j + 2) % 3);

        uint32_t Kb = sbase + QBYTES + (uint32_t)((j % 3) * KVSTG);
        uint32_t Vb = Kb + 64 * 136 * 2;

        float s_acc[8][4];
#pragma unroll
        for (int nt = 0; nt < 8; nt++)
#pragma unroll
            for (int r = 0; r < 4; r++) s_acc[nt][r] = 0.f;

#pragma unroll
        for (int kk = 0; kk < 8; kk++) {
            const int koff = kk * 16 + (lane >> 4) * 8;
#pragma unroll
            for (int nb = 0; nb < 4; nb++) {
                uint32_t bk[4];
                ldm4(bk, Kb + (uint32_t)((nb*16 + (lane & 15)) * 136 + koff) * 2);
                mma16(s_acc[nb*2+0], qf[kk], bk[0], bk[2]);
                mma16(s_acc[nb*2+1], qf[kk], bk[1], bk[3]);
            }
        }

        if (j >= 2 * br) {
            int q0r = br * 128 + rowbase + g;
            int q1r = q0r + 8;
            int kb0 = j * 64;
#pragma unroll
            for (int nt = 0; nt < 8; nt++) {
                int c0 = kb0 + nt * 8 + t2, c1 = c0 + 1;
                if (c0 > q0r) s_acc[nt][0] = -1e30f;
                if (c1 > q0r) s_acc[nt][1] = -1e30f;
                if (c0 > q1r) s_acc[nt][2] = -1e30f;
                if (c1 > q1r) s_acc[nt][3] = -1e30f;
            }
        }

        float rmax0 = -1e30f, rmax1 = -1e30f;
#pragma unroll
        for (int nt = 0; nt < 8; nt++) {
            rmax0 = fmaxf(rmax0, fmaxf(s_acc[nt][0], s_acc[nt][1]));
            rmax1 = fmaxf(rmax1, fmaxf(s_acc[nt][2], s_acc[nt][3]));
        }
        rmax0 = fmaxf(rmax0, __shfl_xor_sync(0xffffffffu, rmax0, 1));
        rmax0 = fmaxf(rmax0, __shfl_xor_sync(0xffffffffu, rmax0, 2));
        rmax1 = fmaxf(rmax1, __shfl_xor_sync(0xffffffffu, rmax1, 1));
        rmax1 = fmaxf(rmax1, __shfl_xor_sync(0xffffffffu, rmax1, 2));
        float mn0 = fmaxf(m0, rmax0), mn1 = fmaxf(m1, rmax1);
        float alpha0 = __expf(m0 - mn0), alpha1 = __expf(m1 - mn1);

        uint32_t pa[4][4];
        float sum0 = 0.f, sum1 = 0.f;
#pragma unroll
        for (int nt = 0; nt < 8; nt++) {
            float e0 = __expf(s_acc[nt][0] - mn0);
            float e1 = __expf(s_acc[nt][1] - mn0);
            float e2 = __expf(s_acc[nt][2] - mn1);
            float e3 = __expf(s_acc[nt][3] - mn1);
            sum0 += e0 + e1;  sum1 += e2 + e3;
            const int kk2 = nt >> 1, hi = (nt & 1) * 2;
            pa[kk2][hi + 0] = h2u(e0, e1);
            pa[kk2][hi + 1] = h2u(e2, e3);
        }
        sum0 += __shfl_xor_sync(0xffffffffu, sum0, 1);
        sum0 += __shfl_xor_sync(0xffffffffu, sum0, 2);
        sum1 += __shfl_xor_sync(0xffffffffu, sum1, 1);
        sum1 += __shfl_xor_sync(0xffffffffu, sum1, 2);
        l0 = l0 * alpha0 + sum0;  m0 = mn0;
        l1 = l1 * alpha1 + sum1;  m1 = mn1;
#pragma unroll
        for (int nt = 0; nt < 16; nt++) {
            acc[nt][0] *= alpha0;  acc[nt][1] *= alpha0;
            acc[nt][2] *= alpha1;  acc[nt][3] *= alpha1;
        }

#pragma unroll
        for (int kk2 = 0; kk2 < 4; kk2++) {
            const int srow = kk2 * 16 + ((lane >> 3) & 1) * 8 + (lane & 7);
            const int dofb = (lane >> 4) * 8;
#pragma unroll
            for (int db = 0; db < 8; db++) {
                uint32_t bv[4];
                ldm4t(bv, Vb + (uint32_t)(srow * 136 + db * 16 + dofb) * 2);
                mma16(acc[db*2+0], pa[kk2], bv[0], bv[1]);
                mma16(acc[db*2+1], pa[kk2], bv[2], bv[3]);
            }
        }
    }

    float rl0 = 1.f / l0, rl1 = 1.f / l1;
    int row0 = br * 128 + rowbase + g;
    __half* op0 = g_aoh + (size_t)row0 * QCOLS + n * HD;
    __half* op1 = op0 + (size_t)8 * QCOLS;
#pragma unroll
    for (int nt = 0; nt < 16; nt++) {
        int col = nt * 8 + t2;
        *(__half2*)(op0 + col) = __floats2half2_rn(acc[nt][0] * rl0, acc[nt][1] * rl0);
        *(__half2*)(op1 + col) = __floats2half2_rn(acc[nt][2] * rl1, acc[nt][3] * rl1);
    }
}

// =====================================================================
extern "C" void kernel_launch(void* const* d_in, const int* in_sizes, int n_in,
                              void* d_out, int out_size)
{
    const float* x    = (const float*)d_in[0];
    const float* sinp = (const float*)d_in[2];
    const float* cosp = (const float*)d_in[3];
    const float* wq   = (const float*)d_in[4];
    const float* wk   = (const float*)d_in[5];
    const float* wv   = (const float*)d_in[6];
    const float* wo   = (const float*)d_in[7];
    const float* qb   = (const float*)d_in[8];
    const float* kb   = (const float*)d_in[9];
    const float* vb   = (const float*)d_in[10];
    float* out = (float*)d_out;

    __half *xh, *woh, *aoh;
    cudaGetSymbolAddress((void**)&xh,  g_xh);
    cudaGetSymbolAddress((void**)&woh, g_woh);
    cudaGetSymbolAddress((void**)&aoh, g_aoh);

    cudaFuncSetAttribute(gemm_qkv,
                         cudaFuncAttributeMaxDynamicSharedMemorySize, GEMM_SMEM);
    cudaFuncSetAttribute(gemm_h64,
                         cudaFuncAttributeMaxDynamicSharedMemorySize, H_SMEM);
    cudaFuncSetAttribute(flash_h_kernel,
                         cudaFuncAttributeMaxDynamicSharedMemorySize, FLASH_SMEM);

    // ---- merged prepass: all fp16 conversions in one launch ----
    cvt_all_kernel<<<(SEGT + 255)/256, 256>>>(x, wq, wk, wv, wo);

    // ---- fused QKV projection + RoPE ----
    gemm_qkv<<<dim3(T_LEN/128, 36), 128, GEMM_SMEM>>>(xh, qb, kb, vb, sinp, cosp);

    // ---- flash attention (heavy blocks first) ----
    flash_h_kernel<<<dim3(T_LEN/128, NHEADS), 256, FLASH_SMEM>>>();

    // ---- output projection -> d_out (128x64 tiles, 3 CTAs/SM) ----
    gemm_h64<<<dim3(T_LEN/128, D_DIM/64), 128, H_SMEM>>>(aoh, woh, out, D_DIM, QCOLS);
}